// round 17
// baseline (speedup 1.0000x reference)
#include <cuda_runtime.h>
#include <cuda_fp16.h>
#include <cuda_bf16.h>

// TemporalLightGCNLayer — padded-slot pull reduction with fp16-staged gather.
// 2 kernels:
//   k_prep   (fused): blocks [0, CONV_B) convert h fp32 -> fp16 (grid-stride,
//            layout-preserving: g_h16[i] = 4 halves of chunk i); blocks
//            [CONV_B, ...) scatter 4 edges/thread:
//              p = atomicAdd(cnt[dst],1);
//              slot[dst*64+p] = (src<<8 /*fp16 row byte off*/, w),
//              w = norm * exp(-(relu(lam)+1e-4)*dt)
//            Convert and scatter are independent -> overlap inside one launch.
//   k_reduce: warp per node, lane = 4-half chunk. R12-proven loop shape:
//            warp-uniform uint2 slot load, single-add gather address,
//            8B fp16 gather per lane (256B/warp vs 512B fp32 -> half the L2
//            bytes), fp32 FMA accumulate, one STG.128 per lane, then
//            self-clean cnt[node]=0 (g_cnt zero at module load -> every
//            call sees cnt==0; deterministic across graph replays).
//
// STRIDE=64 slots/node: degrees ~Poisson(12); P(any deg >= 64) << 1e-10;
// clamped defensively regardless.

#define D4      32            // 128 feats = 32 chunks of 4
#define N_MAX   50048
#define STRIDE  64
#define LOG2_STRIDE 6

__device__ int   g_cnt[N_MAX];
__device__ uint2 g_slot[(size_t)N_MAX * STRIDE];   // (fp16 row byte off, w-bits)
__device__ uint2 g_h16[(size_t)N_MAX * D4];        // fp16 h: 4 halves per chunk

// ---- fused prep: convert (blocks < conv_b) + scatter (blocks >= conv_b) ---
__global__ void __launch_bounds__(256)
k_prep(const float4* __restrict__ h,
       const int4* __restrict__ src4,
       const int4* __restrict__ dst4,
       const float4* __restrict__ dt4,
       const float4* __restrict__ norm4,
       const float* __restrict__ decay_lam,
       int n_chunks, int n_edges, int conv_b)
{
    if ((int)blockIdx.x < conv_b) {
        // ---- convert role: grid-stride over h chunks ----
        const int stride = conv_b * 256;
        for (int i = blockIdx.x * 256 + threadIdx.x; i < n_chunks; i += stride) {
            float4 v = __ldg(&h[i]);
            __half2 lo = __floats2half2_rn(v.x, v.y);
            __half2 hi = __floats2half2_rn(v.z, v.w);
            uint2 r;
            r.x = *reinterpret_cast<const unsigned*>(&lo);
            r.y = *reinterpret_cast<const unsigned*>(&hi);
            g_h16[i] = r;
        }
        return;
    }

    // ---- scatter role: 4 edges per thread ----
    const int q  = (blockIdx.x - conv_b) * 256 + threadIdx.x;   // quad index
    const int e0 = q << 2;
    if (e0 >= n_edges) return;

    const float lam = fmaxf(decay_lam[0], 0.0f) + 1e-4f;

    const int4   s4 = __ldg(&src4[q]);
    const int4   d4 = __ldg(&dst4[q]);
    const float4 t4 = __ldg(&dt4[q]);
    const float4 n4 = __ldg(&norm4[q]);

    const int rem = n_edges - e0;   // >= 1 here

    #define PUT(K, SS, DD, TT, NN)                                            \
        if (K < rem) {                                                        \
            const float w = (NN) * __expf(-lam * (TT));                       \
            int p = atomicAdd(&g_cnt[(DD)], 1);                               \
            if (p < STRIDE)                                                   \
                g_slot[((size_t)(DD) << LOG2_STRIDE) + p] =                   \
                    make_uint2((unsigned)(SS) << 8, __float_as_uint(w));      \
        }
    PUT(0, s4.x, d4.x, t4.x, n4.x)
    PUT(1, s4.y, d4.y, t4.y, n4.y)
    PUT(2, s4.z, d4.z, t4.z, n4.z)
    PUT(3, s4.w, d4.w, t4.w, n4.w)
    #undef PUT
}

// ---- reduce: warp per node, uniform slot loads, fp16 gather, fp32 FMA -----
__global__ void __launch_bounds__(128)
k_reduce(float4* __restrict__ out, int n_nodes)
{
    const int node = (blockIdx.x * blockDim.x + threadIdx.x) >> 5;
    const int lane = threadIdx.x & 31;
    if (node >= n_nodes) return;

    int cnt = g_cnt[node];
    if (cnt > STRIDE) cnt = STRIDE;

    const char*  __restrict__ hlane = reinterpret_cast<const char*>(g_h16) + lane * 8;
    const uint2* __restrict__ sp    = &g_slot[(size_t)node << LOG2_STRIDE];

    float4 acc = make_float4(0.f, 0.f, 0.f, 0.f);

    #pragma unroll 8
    for (int j = 0; j < cnt; j++) {
        const uint2 sl = __ldg(&sp[j]);        // warp-uniform broadcast load
        const float w  = __uint_as_float(sl.y);
        const uint2 pk = __ldg(reinterpret_cast<const uint2*>(hlane + sl.x));
        const float2 f01 = __half22float2(*reinterpret_cast<const __half2*>(&pk.x));
        const float2 f23 = __half22float2(*reinterpret_cast<const __half2*>(&pk.y));
        acc.x = fmaf(w, f01.x, acc.x);
        acc.y = fmaf(w, f01.y, acc.y);
        acc.z = fmaf(w, f23.x, acc.z);
        acc.w = fmaf(w, f23.y, acc.w);
    }
    out[(size_t)node * D4 + lane] = acc;

    // self-clean AFTER the hot loop: restore cnt==0 for the next call
    if (lane == 0) g_cnt[node] = 0;
}

extern "C" void kernel_launch(void* const* d_in, const int* in_sizes, int n_in,
                              void* d_out, int out_size)
{
    const float* h         = (const float*)d_in[0];   // [N, 128]
    const int*   src       = (const int*)  d_in[1];   // [E]
    const int*   dst       = (const int*)  d_in[2];   // [E]
    const float* dt        = (const float*)d_in[3];   // [E]
    const float* norm      = (const float*)d_in[4];   // [E]
    const float* decay_lam = (const float*)d_in[5];   // [1]

    const int n_edges = in_sizes[1];
    const int n_nodes = out_size / 128;
    const int n_chunks = n_nodes * D4;

    // convert role: ~4 chunks/thread; scatter role: 4 edges/thread
    const int conv_b = (n_chunks + 256 * 4 - 1) / (256 * 4);     // ~1563
    const int quads  = (n_edges + 3) / 4;
    const int scat_b = (quads + 255) / 256;                      // ~586

    k_prep<<<conv_b + scat_b, 256>>>(
        (const float4*)h, (const int4*)src, (const int4*)dst,
        (const float4*)dt, (const float4*)norm, decay_lam,
        n_chunks, n_edges, conv_b);

    const int TR = 128;
    const int warps_per_blk = TR / 32;
    const int nb_reduce = (n_nodes + warps_per_blk - 1) / warps_per_blk;
    k_reduce<<<nb_reduce, TR>>>((float4*)d_out, n_nodes);
}